// round 1
// baseline (speedup 1.0000x reference)
#include <cuda_runtime.h>
#include <math.h>

#define NN 1024
#define DNF 128   // node feature dim
#define G3 384    // 3*DNF

// ---------------- device scratch (static allocation only) ----------------
__device__ float g_er[NN * DNF];      // adj-weighted e reduction
__device__ float g_ce[NN * DNF];      // er @ w_msg_e^T + b_msg   (layer-invariant)
__device__ float g_hm[NN * DNF];      // h @ w_msg_h^T
__device__ float g_m [NN * DNF];      // messages
__device__ float g_h [NN * DNF];      // current node state
__device__ float g_gi[NN * G3];       // GRU input gates  (reused as gate_pre in readout)
__device__ float g_gh[NN * G3];       // GRU hidden gates (reused as out_pre in readout)
__device__ int   g_nzi[NN * NN];      // compacted adjacency: column indices
__device__ float g_nzv[NN * NN];      // compacted adjacency: values
__device__ int   g_nzc[NN];           // per-row nonzero count
__device__ float g_part[64 * DNF];    // readout partial sums

// ---------------------------------------------------------------------------
// Kernel 1: per-row adjacency compaction (deterministic order) + adj-weighted
// reduction of e:  er[i,f] = sum_j adj[i,j] * e[i,j,f]
// block = row i, 256 threads
// ---------------------------------------------------------------------------
__global__ void k_build_ereduce(const float* __restrict__ adj,
                                const float* __restrict__ e) {
    const int i   = blockIdx.x;
    const int tid = threadIdx.x;
    const int lane = tid & 31;
    const int w    = tid >> 5;           // 8 warps

    __shared__ int   s_idx[NN];
    __shared__ float s_val[NN];
    __shared__ int   s_wcnt[8];
    __shared__ int   s_woff[8];
    __shared__ int   s_cnt;
    __shared__ float s_red[256];

    const float* arow = adj + (size_t)i * NN;
    const int base = w * 128;

    float av[4];
    unsigned mm[4];
#pragma unroll
    for (int c = 0; c < 4; c++) av[c] = arow[base + c * 32 + lane];
    int tot = 0;
#pragma unroll
    for (int c = 0; c < 4; c++) {
        mm[c] = __ballot_sync(0xffffffffu, av[c] != 0.0f);
        tot += __popc(mm[c]);
    }
    if (lane == 0) s_wcnt[w] = tot;
    __syncthreads();
    if (tid == 0) {
        int run = 0;
        for (int ww = 0; ww < 8; ww++) { s_woff[ww] = run; run += s_wcnt[ww]; }
        s_cnt = run;
    }
    __syncthreads();

    int off = s_woff[w];
    const unsigned lm = (1u << lane) - 1u;
#pragma unroll
    for (int c = 0; c < 4; c++) {
        if (av[c] != 0.0f) {
            int p = off + __popc(mm[c] & lm);
            s_idx[p] = base + c * 32 + lane;
            s_val[p] = av[c];
        }
        off += __popc(mm[c]);
    }
    __syncthreads();

    const int cnt = s_cnt;
    if (tid == 0) g_nzc[i] = cnt;
    for (int k = tid; k < cnt; k += 256) {
        g_nzi[(size_t)i * NN + k] = s_idx[k];
        g_nzv[(size_t)i * NN + k] = s_val[k];
    }

    // adj-weighted gather-reduce of e (2 groups of 128 threads, fixed order)
    const int f = tid & 127;
    const int grp = tid >> 7;
    const float* ebase = e + (size_t)i * NN * DNF;
    float acc = 0.0f;
    for (int k = grp; k < cnt; k += 2)
        acc += s_val[k] * ebase[(size_t)s_idx[k] * DNF + f];
    s_red[tid] = acc;
    __syncthreads();
    if (tid < 128)
        g_er[(size_t)i * DNF + tid] = s_red[tid] + s_red[tid + 128];
}

// ---------------------------------------------------------------------------
// Generic K=128 GEMM:  C[M,N] = A[M,K] @ W[N,K]^T (+ bias) (+= if accumulate)
// Tiles: BM=64, BN=32, BK=64. 256 threads, 4x2 micro-tile per thread.
// Grid: (N/32, M/64). All dims exact multiples — no bounds checks.
// ---------------------------------------------------------------------------
__global__ void k_gemm128(const float* __restrict__ A, int lda,
                          const float* __restrict__ W, int ldw,
                          const float* __restrict__ bias,
                          float* __restrict__ C, int ldc,
                          int accumulate) {
    __shared__ float As[64 * 65];   // [k][row], padded
    __shared__ float Ws[64 * 33];   // [k][col], padded

    const int tid = threadIdx.x;
    const int tx = tid & 15;        // 16 col-groups
    const int ty = tid >> 4;        // 16 row-groups
    const int bm = blockIdx.y * 64;
    const int bn = blockIdx.x * 32;
    const int r0 = ty * 4;
    const int c0 = tx * 2;

    float acc[4][2];
#pragma unroll
    for (int r = 0; r < 4; r++) { acc[r][0] = 0.f; acc[r][1] = 0.f; }

#pragma unroll
    for (int kt = 0; kt < 2; kt++) {
        // stage A tile: 64 rows x 64 k
#pragma unroll
        for (int u = 0; u < 4; u++) {
            int idx = tid + u * 256;
            int row = idx >> 4;
            int kq  = idx & 15;
            float4 v = *(const float4*)(A + (size_t)(bm + row) * lda + kt * 64 + kq * 4);
            As[(kq * 4 + 0) * 65 + row] = v.x;
            As[(kq * 4 + 1) * 65 + row] = v.y;
            As[(kq * 4 + 2) * 65 + row] = v.z;
            As[(kq * 4 + 3) * 65 + row] = v.w;
        }
        // stage W tile: 32 rows x 64 k
#pragma unroll
        for (int u = 0; u < 2; u++) {
            int idx = tid + u * 256;
            int wr = idx >> 4;
            int kq = idx & 15;
            float4 v = *(const float4*)(W + (size_t)(bn + wr) * ldw + kt * 64 + kq * 4);
            Ws[(kq * 4 + 0) * 33 + wr] = v.x;
            Ws[(kq * 4 + 1) * 33 + wr] = v.y;
            Ws[(kq * 4 + 2) * 33 + wr] = v.z;
            Ws[(kq * 4 + 3) * 33 + wr] = v.w;
        }
        __syncthreads();
#pragma unroll
        for (int k = 0; k < 64; k++) {
            float b0 = Ws[k * 33 + c0];
            float b1 = Ws[k * 33 + c0 + 1];
#pragma unroll
            for (int r = 0; r < 4; r++) {
                float a = As[k * 65 + r0 + r];
                acc[r][0] += a * b0;
                acc[r][1] += a * b1;
            }
        }
        __syncthreads();
    }

#pragma unroll
    for (int r = 0; r < 4; r++) {
#pragma unroll
        for (int j = 0; j < 2; j++) {
            int row = bm + r0 + r;
            int col = bn + c0 + j;
            float v = acc[r][j];
            if (bias) v += bias[col];
            float* p = C + (size_t)row * ldc + col;
            if (accumulate) v += *p;
            *p = v;
        }
    }
}

// ---------------------------------------------------------------------------
// SpMV: m[i,d] = sum_k nzv[i,k] * hm[nzi[i,k], d] + ce[i,d]
// block = row i, 256 threads (2 groups x 128 features), deterministic order
// ---------------------------------------------------------------------------
__global__ void k_spmv() {
    const int i   = blockIdx.x;
    const int tid = threadIdx.x;
    const int d   = tid & 127;
    const int grp = tid >> 7;
    __shared__ float s_red[256];

    const int cnt = g_nzc[i];
    const int*   ip = g_nzi + (size_t)i * NN;
    const float* vp = g_nzv + (size_t)i * NN;

    float acc = 0.0f;
    for (int k = grp; k < cnt; k += 2)
        acc += vp[k] * g_hm[(size_t)ip[k] * DNF + d];
    s_red[tid] = acc;
    __syncthreads();
    if (tid < 128)
        g_m[(size_t)i * DNF + tid] = s_red[tid] + s_red[tid + 128]
                                   + g_ce[(size_t)i * DNF + tid];
}

// ---------------------------------------------------------------------------
// GRU elementwise update: h = (1-z)*n + z*h
// ---------------------------------------------------------------------------
__device__ __forceinline__ float sigmoidf_(float x) { return 1.0f / (1.0f + expf(-x)); }

__global__ void k_gru() {
    const int gid = blockIdx.x * blockDim.x + threadIdx.x;   // NN*DNF threads
    const int i = gid >> 7;
    const int d = gid & 127;
    const int b3 = i * G3;
    float r = sigmoidf_(g_gi[b3 + d]        + g_gh[b3 + d]);
    float z = sigmoidf_(g_gi[b3 + 128 + d]  + g_gh[b3 + 128 + d]);
    float n = tanhf   (g_gi[b3 + 256 + d] + r * g_gh[b3 + 256 + d]);
    float h = g_h[gid];
    g_h[gid] = (1.0f - z) * n + z * h;
}

// ---------------------------------------------------------------------------
// Readout partials: part[b,d] = sum over 16 rows of sigmoid(gate)*tanh(out)
// gate_pre in g_gi (ldc=128), out_pre in g_gh (ldc=128). Deterministic order.
// ---------------------------------------------------------------------------
__global__ void k_readout_partial() {
    const int b   = blockIdx.x;    // 64
    const int tid = threadIdx.x;   // 256
    const int d   = tid & 127;
    const int grp = tid >> 7;
    __shared__ float s[256];

    const int i0 = b * 16 + grp * 8;
    float acc = 0.0f;
#pragma unroll
    for (int r = 0; r < 8; r++) {
        int i = i0 + r;
        float gp = g_gi[(size_t)i * DNF + d];
        float op = g_gh[(size_t)i * DNF + d];
        acc += sigmoidf_(gp) * tanhf(op);
    }
    s[tid] = acc;
    __syncthreads();
    if (tid < 128) g_part[b * DNF + tid] = s[tid] + s[tid + 128];
}

// ---------------------------------------------------------------------------
// Final: gv = sum partials; ee = w_embed @ edge; out = w_fc @ [gv,ee] + b_fc
// ---------------------------------------------------------------------------
__global__ void k_final(const float* __restrict__ w_embed,
                        const float* __restrict__ edge,
                        const float* __restrict__ w_fc,
                        const float* __restrict__ b_fc,
                        float* __restrict__ out) {
    const int d = threadIdx.x;   // 128
    __shared__ float s_gv[128];
    __shared__ float s_ee[128];

    float gv = 0.0f;
    for (int b = 0; b < 64; b++) gv += g_part[b * DNF + d];
    s_gv[d] = gv;

    float ee = 0.0f;
#pragma unroll
    for (int f = 0; f < 5; f++) ee += w_embed[d * 5 + f] * edge[f];
    s_ee[d] = ee;
    __syncthreads();

    float acc = b_fc[d];
    const float* wr = w_fc + (size_t)d * 256;
    for (int k = 0; k < 128; k++) acc += wr[k] * s_gv[k];
    for (int k = 0; k < 128; k++) acc += wr[128 + k] * s_ee[k];
    out[d] = acc;
}

// ---------------------------------------------------------------------------
extern "C" void kernel_launch(void* const* d_in, const int* in_sizes, int n_in,
                              void* d_out, int out_size) {
    const float* h       = (const float*)d_in[0];
    const float* e       = (const float*)d_in[1];
    const float* adj     = (const float*)d_in[2];
    const float* edge    = (const float*)d_in[3];
    const float* w_msg_h = (const float*)d_in[4];
    const float* w_msg_e = (const float*)d_in[5];
    const float* b_msg   = (const float*)d_in[6];
    const float* w_ih    = (const float*)d_in[7];
    const float* w_hh    = (const float*)d_in[8];
    const float* b_ih    = (const float*)d_in[9];
    const float* b_hh    = (const float*)d_in[10];
    const float* w_gate  = (const float*)d_in[11];
    const float* b_gate  = (const float*)d_in[12];
    const float* w_out   = (const float*)d_in[13];
    const float* b_out   = (const float*)d_in[14];
    const float* w_embed = (const float*)d_in[15];
    const float* w_fc    = (const float*)d_in[16];
    const float* b_fc    = (const float*)d_in[17];
    float* out = (float*)d_out;

    float *p_er, *p_ce, *p_hm, *p_m, *p_h, *p_gi, *p_gh;
    cudaGetSymbolAddress((void**)&p_er, g_er);
    cudaGetSymbolAddress((void**)&p_ce, g_ce);
    cudaGetSymbolAddress((void**)&p_hm, g_hm);
    cudaGetSymbolAddress((void**)&p_m,  g_m);
    cudaGetSymbolAddress((void**)&p_h,  g_h);
    cudaGetSymbolAddress((void**)&p_gi, g_gi);
    cudaGetSymbolAddress((void**)&p_gh, g_gh);

    const dim3 gN128(128 / 32, NN / 64);   // N=128 GEMMs
    const dim3 gN384(G3  / 32, NN / 64);   // N=384 GEMMs

    // 1) adjacency compaction + adj-weighted e reduction (once)
    k_build_ereduce<<<NN, 256>>>(adj, e);

    // 2) ce = er @ w_msg_e^T + b_msg  (layer-invariant)
    k_gemm128<<<gN128, 256>>>(p_er, 128, w_msg_e, 128, b_msg, p_ce, 128, 0);

    // 3) h <- input h
    cudaMemcpyAsync(p_h, h, (size_t)NN * DNF * sizeof(float),
                    cudaMemcpyDeviceToDevice);

    // 4) message-passing layers
    for (int l = 0; l < 4; l++) {
        k_gemm128<<<gN128, 256>>>(p_h, 128, w_msg_h, 128, nullptr, p_hm, 128, 0);
        k_spmv<<<NN, 256>>>();
        k_gemm128<<<gN384, 256>>>(p_m, 128, w_ih, 128, b_ih, p_gi, G3, 0);
        k_gemm128<<<gN384, 256>>>(p_h, 128, w_hh, 128, b_hh, p_gh, G3, 0);
        k_gru<<<(NN * DNF) / 256, 256>>>();
    }

    // 5) readout: gate_pre/out_pre via split-K-concat GEMM passes
    k_gemm128<<<gN128, 256>>>(p_h, 128, w_gate,       256, b_gate,  p_gi, 128, 0);
    k_gemm128<<<gN128, 256>>>(h,   128, w_gate + 128, 256, nullptr, p_gi, 128, 1);
    k_gemm128<<<gN128, 256>>>(p_h, 128, w_out,        256, b_out,   p_gh, 128, 0);
    k_gemm128<<<gN128, 256>>>(h,   128, w_out + 128,  256, nullptr, p_gh, 128, 1);

    k_readout_partial<<<64, 256>>>();
    k_final<<<1, 128>>>(w_embed, edge, w_fc, b_fc, out);
}